// round 15
// baseline (speedup 1.0000x reference)
#include <cuda_runtime.h>
#include <cuda_fp16.h>
#include <cstdint>

#define NTOK  32768
#define CDIM  512
#define KCOD  1024
#define HW    4096

// ---------------- scratch ----------------------------------------------------
__device__ float               g_rnx[NTOK];
__device__ float               g_rnm[KCOD];
__device__ float               g_rowsum[NTOK];
__device__ unsigned long long  g_amax[NTOK];
__device__ uint32_t            g_xh[NTOK * CDIM / 2];            // half2(x), [b][c/2][s]
__device__ uint32_t            g_mhT[(CDIM / 2) * KCOD];         // half2(m), [c/2][j]
__device__ uint32_t            g_expsH[(size_t)(KCOD / 2) * NTOK]; // half2(exp), [j/2][token]
__device__ float               g_esum[KCOD * CDIM];
__device__ float               g_cnt[KCOD];
__device__ uint32_t            g_newmH[(KCOD / 2) * CDIM];       // half2(new_m), [k/2][c]

// ---------------- helpers -----------------------------------------------------
__device__ __forceinline__ void cp16(void* dst, const void* src) {
    unsigned d = (unsigned)__cvta_generic_to_shared(dst);
    asm volatile("cp.async.cg.shared.global [%0], [%1], 16;" :: "r"(d), "l"(src));
}

#define MMA_F16(d, a, b) \
    asm volatile("mma.sync.aligned.m16n8k16.row.col.f32.f16.f16.f32 " \
        "{%0,%1,%2,%3}, {%4,%5,%6,%7}, {%8,%9}, {%0,%1,%2,%3};" \
        : "+f"(d[0]), "+f"(d[1]), "+f"(d[2]), "+f"(d[3]) \
        : "r"(a[0]), "r"(a[1]), "r"(a[2]), "r"(a[3]), "r"(b[0]), "r"(b[1]))

__device__ __forceinline__ uint32_t pack_h2(float lo, float hi) {
    __half2 h = __floats2half2_rn(lo, hi);
    return *(uint32_t*)&h;
}

__device__ __forceinline__ unsigned long long pack_max(float s, int j) {
    unsigned int bits = __float_as_uint(s);
    unsigned int key  = (bits & 0x80000000u) ? ~bits : (bits | 0x80000000u);
    return ((unsigned long long)key << 32)
         | (unsigned long long)(0xFFFFFFFFu - (unsigned)j);
}

// ---------------- fused: token norms + half2 pack (x read ONCE) ------------------
__global__ void k_norm_pack(const float* __restrict__ x) {
    int i0 = blockIdx.x * 32;
    int b  = i0 >> 12;
    int s0 = i0 & 4095;
    int tx = threadIdx.x, ty = threadIdx.y;   // 32 x 8
    const float* xb = x + (size_t)b * CDIM * HW + s0 + tx;
    uint32_t* xo = g_xh + (size_t)b * (CDIM / 2) * HW + s0 + tx;
    float ss = 0.f;
    for (int p = ty; p < CDIM / 2; p += 8) {
        float v0 = xb[(size_t)(2 * p)     * HW];
        float v1 = xb[(size_t)(2 * p + 1) * HW];
        ss += v0 * v0 + v1 * v1;
        xo[(size_t)p * HW] = pack_h2(v0, v1);
    }
    __shared__ float sm[8][33];
    sm[ty][tx] = ss;
    __syncthreads();
    if (ty == 0) {
        float t = 0.f;
        #pragma unroll
        for (int r = 0; r < 8; r++) t += sm[r][tx];
        g_rnx[i0 + tx] = 1.0f / fmaxf(sqrtf(t), 1e-12f);
    }
}

// ---------------- codebook: norm + half2 transpose -------------------------------
__global__ void k_prep_m(const float* __restrict__ m) {
    int j = blockIdx.x;
    int t = threadIdx.x;
    float v0 = m[j * CDIM + 2 * t];
    float v1 = m[j * CDIM + 2 * t + 1];
    float ss = v0 * v0 + v1 * v1;
    #pragma unroll
    for (int o = 16; o > 0; o >>= 1) ss += __shfl_xor_sync(0xffffffffu, ss, o);
    __shared__ float sm[8];
    if ((t & 31) == 0) sm[t >> 5] = ss;
    __syncthreads();
    if (t == 0) {
        float tt = 0.f;
        #pragma unroll
        for (int w = 0; w < 8; w++) tt += sm[w];
        g_rnm[j] = 1.0f / fmaxf(sqrtf(tt), 1e-12f);
    }
    g_mhT[(size_t)t * KCOD + j] = pack_h2(v0, v1);
}

// ======== GEMM machinery: CTA 128 threads (4 warps, 2m x 2n), tile 128x128, ======
// ======== warp tile 64x64, ktile 64 halfs (32 kpair rows), 3 cp.async stages, ====
// ======== SINGLE barrier per iteration ============================================
// stage: As 32x136 u32 + Bs 32x136 u32
#define STG_U32   8704
#define AS_U32    4352

#define GEMM_ISSUE(Ag, Bg, strideA, strideB, it) do {                        \
    uint32_t* dst = smem + ((it) % 3) * STG_U32;                             \
    int kr0 = (it) * 32;                                                     \
    _Pragma("unroll")                                                        \
    for (int q = 0; q < 8; q++) {                                            \
        int ch = tid + q * 128;                                              \
        int r = ch >> 5, cu = (ch & 31) * 4;                                 \
        cp16(&dst[r * 136 + cu], (Ag) + (size_t)(kr0 + r) * (strideA) + cu); \
        cp16(&dst[AS_U32 + r * 136 + cu],                                    \
             (Bg) + (size_t)(kr0 + r) * (strideB) + cu);                     \
    }                                                                        \
    asm volatile("cp.async.commit_group;");                                  \
} while (0)

#define GEMM_COMPUTE(it) do {                                                \
    const uint32_t* As = smem + ((it) % 3) * STG_U32;                        \
    const uint32_t* Bs = As + AS_U32;                                        \
    _Pragma("unroll")                                                        \
    for (int kp = 0; kp < 32; kp += 8) {                                     \
        uint32_t af[4][4], bf[8][2];                                         \
        _Pragma("unroll")                                                    \
        for (int mt = 0; mt < 4; mt++) {                                     \
            af[mt][0] = As[(kp + tg    ) * 136 + rA + mt * 16    ];          \
            af[mt][1] = As[(kp + tg    ) * 136 + rA + mt * 16 + 8];          \
            af[mt][2] = As[(kp + tg + 4) * 136 + rA + mt * 16    ];          \
            af[mt][3] = As[(kp + tg + 4) * 136 + rA + mt * 16 + 8];          \
        }                                                                    \
        _Pragma("unroll")                                                    \
        for (int nt = 0; nt < 8; nt++) {                                     \
            bf[nt][0] = Bs[(kp + tg    ) * 136 + cB + nt * 8];               \
            bf[nt][1] = Bs[(kp + tg + 4) * 136 + cB + nt * 8];               \
        }                                                                    \
        _Pragma("unroll")                                                    \
        for (int mt = 0; mt < 4; mt++)                                       \
            _Pragma("unroll")                                                \
            for (int nt = 0; nt < 8; nt++)                                   \
                MMA_F16(acc[mt][nt], af[mt], bf[nt]);                        \
    }                                                                        \
} while (0)

// 3-stage, ONE barrier/iter. Safety: issue(it+2) at iter `it` writes stage
// (it+2)%3 == (it-1)%3, whose readers (compute(it-1)) all passed this iter's
// top barrier before any warp reaches issue. wait_group: at top of iter `it`
// pending groups are {it, it+1} (or just {it} on the last iter), so wait 1
// (resp. 0) guarantees stage `it` has landed.
#define GEMM_MAINLOOP(Ag, Bg, strideA, strideB, NIT) do {                    \
    GEMM_ISSUE(Ag, Bg, strideA, strideB, 0);                                 \
    GEMM_ISSUE(Ag, Bg, strideA, strideB, 1);                                 \
    for (int it = 0; it < (NIT); it++) {                                     \
        if (it + 1 < (NIT)) { asm volatile("cp.async.wait_group 1;"); }      \
        else                { asm volatile("cp.async.wait_group 0;"); }      \
        __syncthreads();                                                     \
        if (it + 2 < (NIT)) GEMM_ISSUE(Ag, Bg, strideA, strideB, it + 2);    \
        GEMM_COMPUTE(it);                                                    \
    }                                                                        \
} while (0)

// ---------------- GEMM1: exp(score) + fused rowsum/argmax (fp16 mma) --------------
__global__ void __launch_bounds__(128, 2) k_gemm1() {
    extern __shared__ uint32_t smem[];
    int tid  = threadIdx.x;
    int lane = tid & 31, warp = tid >> 5;      // 4 warps
    int g = lane >> 2, tg = lane & 3;
    int wm = warp >> 1, wn = warp & 1;         // 2m x 2n
    int i0 = blockIdx.y * 128;
    int j0 = blockIdx.x * 128;
    int b  = i0 >> 12, s0 = i0 & 4095;
    const uint32_t* Ag = g_xh + (size_t)b * (CDIM / 2) * HW + s0;
    const uint32_t* Bg = g_mhT + j0;

    float acc[4][8][4] = {};
    const int NIT = CDIM / 64;      // 8
    int rA = wm * 64 + g;
    int cB = wn * 64 + g;

    GEMM_MAINLOOP(Ag, Bg, HW, KCOD, NIT);

    // epilogue (validated numerics)
    int rbase = i0 + wm * 64;
    int cbase = j0 + wn * 64 + 2 * tg;
    float rm0[8], rm1[8];
    #pragma unroll
    for (int nt = 0; nt < 8; nt++) {
        rm0[nt] = g_rnm[cbase + nt * 8];
        rm1[nt] = g_rnm[cbase + nt * 8 + 1];
    }
    #pragma unroll
    for (int mt = 0; mt < 4; mt++) {
        int r0 = rbase + mt * 16 + g;
        int r1 = r0 + 8;
        float rx0 = g_rnx[r0], rx1 = g_rnx[r1];
        float sum0 = 0.f, sum1 = 0.f;
        float best0 = -2.f, best1 = -2.f;
        int bj0 = cbase, bj1 = cbase;
        #pragma unroll
        for (int nt = 0; nt < 8; nt++) {
            int c = cbase + nt * 8;
            float s00 = acc[mt][nt][0] * rx0 * rm0[nt];
            float s01 = acc[mt][nt][1] * rx0 * rm1[nt];
            float s10 = acc[mt][nt][2] * rx1 * rm0[nt];
            float s11 = acc[mt][nt][3] * rx1 * rm1[nt];
            float e00 = __expf(s00), e01 = __expf(s01);
            float e10 = __expf(s10), e11 = __expf(s11);
            size_t cp = (size_t)(c >> 1) * NTOK;
            g_expsH[cp + r0] = pack_h2(e00, e01);
            g_expsH[cp + r1] = pack_h2(e10, e11);
            sum0 += e00 + e01; sum1 += e10 + e11;
            if (s00 > best0) { best0 = s00; bj0 = c; }
            if (s01 > best0) { best0 = s01; bj0 = c + 1; }
            if (s10 > best1) { best1 = s10; bj1 = c; }
            if (s11 > best1) { best1 = s11; bj1 = c + 1; }
        }
        unsigned long long p0 = pack_max(best0, bj0);
        unsigned long long p1 = pack_max(best1, bj1);
        #pragma unroll
        for (int o = 1; o < 4; o <<= 1) {
            sum0 += __shfl_xor_sync(0xffffffffu, sum0, o);
            sum1 += __shfl_xor_sync(0xffffffffu, sum1, o);
            unsigned long long q0 = __shfl_xor_sync(0xffffffffu, p0, o);
            unsigned long long q1 = __shfl_xor_sync(0xffffffffu, p1, o);
            if (q0 > p0) p0 = q0;
            if (q1 > p1) p1 = q1;
        }
        if (tg == 0) {
            atomicAdd(&g_rowsum[r0], sum0);
            atomicAdd(&g_rowsum[r1], sum1);
            atomicMax(&g_amax[r0], p0);
            atomicMax(&g_amax[r1], p1);
        }
    }
}

// ---------------- scatter: half2 reads + red.v4 vector reductions ------------------
__global__ void k_scatter() {
    int i0 = blockIdx.x * 32;
    int b  = i0 >> 12, s0 = i0 & 4095;
    int tx = threadIdx.x, ty = threadIdx.y;   // 32 x 8
    __shared__ int sidx[32];
    int tid = ty * 32 + tx;
    if (tid < 32) {
        unsigned long long p = g_amax[i0 + tid];
        int idx = (int)(0xFFFFFFFFu - (unsigned)(p & 0xFFFFFFFFull));
        sidx[tid] = idx;
        atomicAdd(&g_cnt[idx], 1.0f);
    }
    __syncthreads();
    int idx = sidx[tx];
    const uint32_t* xb = g_xh + (size_t)b * (CDIM / 2) * HW + s0 + tx;
    float* erow = g_esum + (size_t)idx * CDIM;
    for (int q = ty; q < CDIM / 4; q += 8) {
        uint32_t u0 = xb[(size_t)(2 * q)     * HW];
        uint32_t u1 = xb[(size_t)(2 * q + 1) * HW];
        __half2 h0 = *(__half2*)&u0;
        __half2 h1 = *(__half2*)&u1;
        float c0 = __low2float(h0), c1 = __high2float(h0);
        float c2 = __low2float(h1), c3 = __high2float(h1);
        asm volatile("red.global.add.v4.f32 [%0], {%1, %2, %3, %4};"
                     :: "l"(erow + 4 * q), "f"(c0), "f"(c1), "f"(c2), "f"(c3)
                     : "memory");
    }
}

// ---------------- EMA update -> half2 pairs along k -------------------------------
__global__ void k_update(const float* __restrict__ m) {
    int kp = blockIdx.x;
    int k0 = 2 * kp, k1 = k0 + 1;
    float inv0 = 0.001f / (g_cnt[k0] + 1e-6f);
    float inv1 = 0.001f / (g_cnt[k1] + 1e-6f);
    for (int j = threadIdx.x; j < CDIM; j += blockDim.x) {
        float v0 = m[k0 * CDIM + j] * 0.999f + g_esum[k0 * CDIM + j] * inv0;
        float v1 = m[k1 * CDIM + j] * 0.999f + g_esum[k1 * CDIM + j] * inv1;
        g_newmH[(size_t)kp * CDIM + j] = pack_h2(v0, v1);
    }
}

// ---------------- GEMM2: out = (exps @ new_m) / rowsum (fp16 mma) ------------------
__global__ void __launch_bounds__(128, 2) k_gemm2(float* __restrict__ out) {
    extern __shared__ uint32_t smem[];
    int tid  = threadIdx.x;
    int lane = tid & 31, warp = tid >> 5;
    int g = lane >> 2, tg = lane & 3;
    int wm = warp >> 1, wn = warp & 1;
    int i0 = blockIdx.y * 128;   // tokens
    int j0 = blockIdx.x * 128;   // channels

    const uint32_t* Ag = g_expsH + i0;
    const uint32_t* Bg = g_newmH + j0;

    float acc[4][8][4] = {};
    const int NIT = KCOD / 64;           // 16
    int rA = wm * 64 + g;
    int cB = wn * 64 + g;

    GEMM_MAINLOOP(Ag, Bg, NTOK, CDIM, NIT);

    int b = i0 >> 12;
    int rbase = i0 + wm * 64;
    int cbase = j0 + wn * 64 + 2 * tg;
    #pragma unroll
    for (int mt = 0; mt < 4; mt++) {
        int r0 = rbase + mt * 16 + g;
        int r1 = r0 + 8;
        float ri0 = 1.0f / g_rowsum[r0];
        float ri1 = 1.0f / g_rowsum[r1];
        int sA = r0 & 4095, sB = r1 & 4095;
        #pragma unroll
        for (int nt = 0; nt < 8; nt++) {
            int c = cbase + nt * 8;
            out[(size_t)(b * CDIM + c    ) * HW + sA] = acc[mt][nt][0] * ri0;
            out[(size_t)(b * CDIM + c + 1) * HW + sA] = acc[mt][nt][1] * ri0;
            out[(size_t)(b * CDIM + c    ) * HW + sB] = acc[mt][nt][2] * ri1;
            out[(size_t)(b * CDIM + c + 1) * HW + sB] = acc[mt][nt][3] * ri1;
        }
    }
}

// ---------------- launch -------------------------------------------------------------
extern "C" void kernel_launch(void* const* d_in, const int* in_sizes, int n_in,
                              void* d_out, int out_size) {
    const float* x = (const float*)d_in[0];
    const float* m = (const float*)d_in[1];
    float* out = (float*)d_out;

    const int SMEM = 3 * STG_U32 * 4;   // 104448 B per CTA
    cudaFuncSetAttribute(k_gemm1, cudaFuncAttributeMaxDynamicSharedMemorySize, SMEM);
    cudaFuncSetAttribute(k_gemm2, cudaFuncAttributeMaxDynamicSharedMemorySize, SMEM);

    // zero accumulators via memset nodes (no alloc; graph-capturable)
    void *p_esum, *p_cnt, *p_rowsum, *p_amax;
    cudaGetSymbolAddress(&p_esum,   g_esum);
    cudaGetSymbolAddress(&p_cnt,    g_cnt);
    cudaGetSymbolAddress(&p_rowsum, g_rowsum);
    cudaGetSymbolAddress(&p_amax,   g_amax);
    cudaMemsetAsync(p_esum,   0, (size_t)KCOD * CDIM * sizeof(float));
    cudaMemsetAsync(p_cnt,    0, (size_t)KCOD * sizeof(float));
    cudaMemsetAsync(p_rowsum, 0, (size_t)NTOK * sizeof(float));
    cudaMemsetAsync(p_amax,   0, (size_t)NTOK * sizeof(unsigned long long));

    k_norm_pack<<<NTOK / 32, dim3(32, 8)>>>(x);
    k_prep_m<<<KCOD, 256>>>(m);
    k_gemm1<<<dim3(KCOD / 128, NTOK / 128), 128, SMEM>>>();
    k_scatter<<<NTOK / 32, dim3(32, 8)>>>();
    k_update<<<KCOD / 2, 256>>>(m);
    k_gemm2<<<dim3(CDIM / 128, NTOK / 128), 128, SMEM>>>(out);
}

// round 16
// speedup vs baseline: 1.0095x; 1.0095x over previous
#include <cuda_runtime.h>
#include <cuda_fp16.h>
#include <cstdint>

#define NTOK  32768
#define CDIM  512
#define KCOD  1024
#define HW    4096

// ---------------- scratch ----------------------------------------------------
__device__ float               g_rnx[NTOK];
__device__ float               g_rnm[KCOD];
__device__ float               g_rowsum[NTOK];
__device__ unsigned long long  g_amax[NTOK];
__device__ uint32_t            g_xh[NTOK * CDIM / 2];            // half2(x), [b][c/2][s]
__device__ uint32_t            g_mhT[(CDIM / 2) * KCOD];         // half2(m), [c/2][j]
__device__ uint32_t            g_expsH[(size_t)(KCOD / 2) * NTOK]; // half2(exp), [j/2][token]
__device__ float               g_esum[KCOD * CDIM];
__device__ float               g_cnt[KCOD];
__device__ uint32_t            g_newmH[(KCOD / 2) * CDIM];       // half2(new_m), [k/2][c]

// ---------------- helpers -----------------------------------------------------
__device__ __forceinline__ void cp16(void* dst, const void* src) {
    unsigned d = (unsigned)__cvta_generic_to_shared(dst);
    asm volatile("cp.async.cg.shared.global [%0], [%1], 16;" :: "r"(d), "l"(src));
}

#define MMA_F16(d, a, b) \
    asm volatile("mma.sync.aligned.m16n8k16.row.col.f32.f16.f16.f32 " \
        "{%0,%1,%2,%3}, {%4,%5,%6,%7}, {%8,%9}, {%0,%1,%2,%3};" \
        : "+f"(d[0]), "+f"(d[1]), "+f"(d[2]), "+f"(d[3]) \
        : "r"(a[0]), "r"(a[1]), "r"(a[2]), "r"(a[3]), "r"(b[0]), "r"(b[1]))

__device__ __forceinline__ uint32_t pack_h2(float lo, float hi) {
    __half2 h = __floats2half2_rn(lo, hi);
    return *(uint32_t*)&h;
}

__device__ __forceinline__ unsigned long long pack_max(float s, int j) {
    unsigned int bits = __float_as_uint(s);
    unsigned int key  = (bits & 0x80000000u) ? ~bits : (bits | 0x80000000u);
    return ((unsigned long long)key << 32)
         | (unsigned long long)(0xFFFFFFFFu - (unsigned)j);
}

// ---------------- fused: token norms + half2 pack (x read ONCE) ------------------
__global__ void k_norm_pack(const float* __restrict__ x) {
    int i0 = blockIdx.x * 32;
    int b  = i0 >> 12;
    int s0 = i0 & 4095;
    int tx = threadIdx.x, ty = threadIdx.y;   // 32 x 8
    const float* xb = x + (size_t)b * CDIM * HW + s0 + tx;
    uint32_t* xo = g_xh + (size_t)b * (CDIM / 2) * HW + s0 + tx;
    float ss = 0.f;
    for (int p = ty; p < CDIM / 2; p += 8) {
        float v0 = xb[(size_t)(2 * p)     * HW];
        float v1 = xb[(size_t)(2 * p + 1) * HW];
        ss += v0 * v0 + v1 * v1;
        xo[(size_t)p * HW] = pack_h2(v0, v1);
    }
    __shared__ float sm[8][33];
    sm[ty][tx] = ss;
    __syncthreads();
    if (ty == 0) {
        float t = 0.f;
        #pragma unroll
        for (int r = 0; r < 8; r++) t += sm[r][tx];
        g_rnx[i0 + tx] = 1.0f / fmaxf(sqrtf(t), 1e-12f);
    }
}

// ---------------- codebook: norm + half2 transpose -------------------------------
__global__ void k_prep_m(const float* __restrict__ m) {
    int j = blockIdx.x;
    int t = threadIdx.x;
    float v0 = m[j * CDIM + 2 * t];
    float v1 = m[j * CDIM + 2 * t + 1];
    float ss = v0 * v0 + v1 * v1;
    #pragma unroll
    for (int o = 16; o > 0; o >>= 1) ss += __shfl_xor_sync(0xffffffffu, ss, o);
    __shared__ float sm[8];
    if ((t & 31) == 0) sm[t >> 5] = ss;
    __syncthreads();
    if (t == 0) {
        float tt = 0.f;
        #pragma unroll
        for (int w = 0; w < 8; w++) tt += sm[w];
        g_rnm[j] = 1.0f / fmaxf(sqrtf(tt), 1e-12f);
    }
    g_mhT[(size_t)t * KCOD + j] = pack_h2(v0, v1);
}

// ======== GEMM machinery (R14 proven): CTA 128 threads (4 warps, 2m x 2n), =======
// ======== tile 128x128, warp tile 64x64, ktile 64 halfs, 2 cp.async stages =======
// stage: As 32x136 u32 + Bs 32x136 u32
#define STG_U32   8704
#define AS_U32    4352

#define GEMM_ISSUE(Ag, Bg, strideA, strideB, it) do {                        \
    uint32_t* dst = smem + ((it) & 1) * STG_U32;                             \
    int kr0 = (it) * 32;                                                     \
    _Pragma("unroll")                                                        \
    for (int q = 0; q < 8; q++) {                                            \
        int ch = tid + q * 128;                                              \
        int r = ch >> 5, cu = (ch & 31) * 4;                                 \
        cp16(&dst[r * 136 + cu], (Ag) + (size_t)(kr0 + r) * (strideA) + cu); \
        cp16(&dst[AS_U32 + r * 136 + cu],                                    \
             (Bg) + (size_t)(kr0 + r) * (strideB) + cu);                     \
    }                                                                        \
    asm volatile("cp.async.commit_group;");                                  \
} while (0)

#define GEMM_COMPUTE(it) do {                                                \
    const uint32_t* As = smem + ((it) & 1) * STG_U32;                        \
    const uint32_t* Bs = As + AS_U32;                                        \
    _Pragma("unroll")                                                        \
    for (int kp = 0; kp < 32; kp += 8) {                                     \
        uint32_t af[4][4], bf[8][2];                                         \
        _Pragma("unroll")                                                    \
        for (int mt = 0; mt < 4; mt++) {                                     \
            af[mt][0] = As[(kp + tg    ) * 136 + rA + mt * 16    ];          \
            af[mt][1] = As[(kp + tg    ) * 136 + rA + mt * 16 + 8];          \
            af[mt][2] = As[(kp + tg + 4) * 136 + rA + mt * 16    ];          \
            af[mt][3] = As[(kp + tg + 4) * 136 + rA + mt * 16 + 8];          \
        }                                                                    \
        _Pragma("unroll")                                                    \
        for (int nt = 0; nt < 8; nt++) {                                     \
            bf[nt][0] = Bs[(kp + tg    ) * 136 + cB + nt * 8];               \
            bf[nt][1] = Bs[(kp + tg + 4) * 136 + cB + nt * 8];               \
        }                                                                    \
        _Pragma("unroll")                                                    \
        for (int mt = 0; mt < 4; mt++)                                       \
            _Pragma("unroll")                                                \
            for (int nt = 0; nt < 8; nt++)                                   \
                MMA_F16(acc[mt][nt], af[mt], bf[nt]);                        \
    }                                                                        \
} while (0)

// 2-stage pipeline: wait -> compute -> barrier -> refill freed stage (R14 exact)
#define GEMM_MAINLOOP(Ag, Bg, strideA, strideB, NIT) do {                    \
    GEMM_ISSUE(Ag, Bg, strideA, strideB, 0);                                 \
    GEMM_ISSUE(Ag, Bg, strideA, strideB, 1);                                 \
    for (int it = 0; it < (NIT); it++) {                                     \
        if (it + 1 < (NIT)) { asm volatile("cp.async.wait_group 1;"); }      \
        else                { asm volatile("cp.async.wait_group 0;"); }      \
        __syncthreads();                                                     \
        GEMM_COMPUTE(it);                                                    \
        __syncthreads();                                                     \
        if (it + 2 < (NIT)) GEMM_ISSUE(Ag, Bg, strideA, strideB, it + 2);    \
    }                                                                        \
} while (0)

// ---------------- GEMM1: exp(score) + fused rowsum/argmax (fp16 mma) --------------
__global__ void __launch_bounds__(128, 2) k_gemm1() {
    extern __shared__ uint32_t smem[];
    int tid  = threadIdx.x;
    int lane = tid & 31, warp = tid >> 5;      // 4 warps
    int g = lane >> 2, tg = lane & 3;
    int wm = warp >> 1, wn = warp & 1;         // 2m x 2n
    int i0 = blockIdx.y * 128;
    int j0 = blockIdx.x * 128;
    int b  = i0 >> 12, s0 = i0 & 4095;
    const uint32_t* Ag = g_xh + (size_t)b * (CDIM / 2) * HW + s0;
    const uint32_t* Bg = g_mhT + j0;

    float acc[4][8][4] = {};
    const int NIT = CDIM / 64;      // 8
    int rA = wm * 64 + g;
    int cB = wn * 64 + g;

    GEMM_MAINLOOP(Ag, Bg, HW, KCOD, NIT);

    // epilogue (validated numerics)
    int rbase = i0 + wm * 64;
    int cbase = j0 + wn * 64 + 2 * tg;
    float rm0[8], rm1[8];
    #pragma unroll
    for (int nt = 0; nt < 8; nt++) {
        rm0[nt] = g_rnm[cbase + nt * 8];
        rm1[nt] = g_rnm[cbase + nt * 8 + 1];
    }
    #pragma unroll
    for (int mt = 0; mt < 4; mt++) {
        int r0 = rbase + mt * 16 + g;
        int r1 = r0 + 8;
        float rx0 = g_rnx[r0], rx1 = g_rnx[r1];
        float sum0 = 0.f, sum1 = 0.f;
        float best0 = -2.f, best1 = -2.f;
        int bj0 = cbase, bj1 = cbase;
        #pragma unroll
        for (int nt = 0; nt < 8; nt++) {
            int c = cbase + nt * 8;
            float s00 = acc[mt][nt][0] * rx0 * rm0[nt];
            float s01 = acc[mt][nt][1] * rx0 * rm1[nt];
            float s10 = acc[mt][nt][2] * rx1 * rm0[nt];
            float s11 = acc[mt][nt][3] * rx1 * rm1[nt];
            float e00 = __expf(s00), e01 = __expf(s01);
            float e10 = __expf(s10), e11 = __expf(s11);
            size_t cp = (size_t)(c >> 1) * NTOK;
            g_expsH[cp + r0] = pack_h2(e00, e01);
            g_expsH[cp + r1] = pack_h2(e10, e11);
            sum0 += e00 + e01; sum1 += e10 + e11;
            if (s00 > best0) { best0 = s00; bj0 = c; }
            if (s01 > best0) { best0 = s01; bj0 = c + 1; }
            if (s10 > best1) { best1 = s10; bj1 = c; }
            if (s11 > best1) { best1 = s11; bj1 = c + 1; }
        }
        unsigned long long p0 = pack_max(best0, bj0);
        unsigned long long p1 = pack_max(best1, bj1);
        #pragma unroll
        for (int o = 1; o < 4; o <<= 1) {
            sum0 += __shfl_xor_sync(0xffffffffu, sum0, o);
            sum1 += __shfl_xor_sync(0xffffffffu, sum1, o);
            unsigned long long q0 = __shfl_xor_sync(0xffffffffu, p0, o);
            unsigned long long q1 = __shfl_xor_sync(0xffffffffu, p1, o);
            if (q0 > p0) p0 = q0;
            if (q1 > p1) p1 = q1;
        }
        if (tg == 0) {
            atomicAdd(&g_rowsum[r0], sum0);
            atomicAdd(&g_rowsum[r1], sum1);
            atomicMax(&g_amax[r0], p0);
            atomicMax(&g_amax[r1], p1);
        }
    }
}

// ---------------- scatter: half2 reads + red.v4 vector reductions ------------------
__global__ void k_scatter() {
    int i0 = blockIdx.x * 32;
    int b  = i0 >> 12, s0 = i0 & 4095;
    int tx = threadIdx.x, ty = threadIdx.y;   // 32 x 8
    __shared__ int sidx[32];
    int tid = ty * 32 + tx;
    if (tid < 32) {
        unsigned long long p = g_amax[i0 + tid];
        int idx = (int)(0xFFFFFFFFu - (unsigned)(p & 0xFFFFFFFFull));
        sidx[tid] = idx;
        atomicAdd(&g_cnt[idx], 1.0f);
    }
    __syncthreads();
    int idx = sidx[tx];
    const uint32_t* xb = g_xh + (size_t)b * (CDIM / 2) * HW + s0 + tx;
    float* erow = g_esum + (size_t)idx * CDIM;
    for (int q = ty; q < CDIM / 4; q += 8) {
        uint32_t u0 = xb[(size_t)(2 * q)     * HW];
        uint32_t u1 = xb[(size_t)(2 * q + 1) * HW];
        __half2 h0 = *(__half2*)&u0;
        __half2 h1 = *(__half2*)&u1;
        float c0 = __low2float(h0), c1 = __high2float(h0);
        float c2 = __low2float(h1), c3 = __high2float(h1);
        asm volatile("red.global.add.v4.f32 [%0], {%1, %2, %3, %4};"
                     :: "l"(erow + 4 * q), "f"(c0), "f"(c1), "f"(c2), "f"(c3)
                     : "memory");
    }
}

// ---------------- EMA update -> half2 pairs along k -------------------------------
__global__ void k_update(const float* __restrict__ m) {
    int kp = blockIdx.x;
    int k0 = 2 * kp, k1 = k0 + 1;
    float inv0 = 0.001f / (g_cnt[k0] + 1e-6f);
    float inv1 = 0.001f / (g_cnt[k1] + 1e-6f);
    for (int j = threadIdx.x; j < CDIM; j += blockDim.x) {
        float v0 = m[k0 * CDIM + j] * 0.999f + g_esum[k0 * CDIM + j] * inv0;
        float v1 = m[k1 * CDIM + j] * 0.999f + g_esum[k1 * CDIM + j] * inv1;
        g_newmH[(size_t)kp * CDIM + j] = pack_h2(v0, v1);
    }
}

// ---------------- GEMM2: out = (exps @ new_m) / rowsum (fp16 mma) ------------------
__global__ void __launch_bounds__(128, 2) k_gemm2(float* __restrict__ out) {
    extern __shared__ uint32_t smem[];
    int tid  = threadIdx.x;
    int lane = tid & 31, warp = tid >> 5;
    int g = lane >> 2, tg = lane & 3;
    int wm = warp >> 1, wn = warp & 1;
    int i0 = blockIdx.y * 128;   // tokens
    int j0 = blockIdx.x * 128;   // channels

    const uint32_t* Ag = g_expsH + i0;
    const uint32_t* Bg = g_newmH + j0;

    float acc[4][8][4] = {};
    const int NIT = KCOD / 64;           // 16
    int rA = wm * 64 + g;
    int cB = wn * 64 + g;

    GEMM_MAINLOOP(Ag, Bg, NTOK, CDIM, NIT);

    int b = i0 >> 12;
    int rbase = i0 + wm * 64;
    int cbase = j0 + wn * 64 + 2 * tg;
    #pragma unroll
    for (int mt = 0; mt < 4; mt++) {
        int r0 = rbase + mt * 16 + g;
        int r1 = r0 + 8;
        float ri0 = 1.0f / g_rowsum[r0];
        float ri1 = 1.0f / g_rowsum[r1];
        int sA = r0 & 4095, sB = r1 & 4095;
        #pragma unroll
        for (int nt = 0; nt < 8; nt++) {
            int c = cbase + nt * 8;
            out[(size_t)(b * CDIM + c    ) * HW + sA] = acc[mt][nt][0] * ri0;
            out[(size_t)(b * CDIM + c + 1) * HW + sA] = acc[mt][nt][1] * ri0;
            out[(size_t)(b * CDIM + c    ) * HW + sB] = acc[mt][nt][2] * ri1;
            out[(size_t)(b * CDIM + c + 1) * HW + sB] = acc[mt][nt][3] * ri1;
        }
    }
}

// ---------------- launch -------------------------------------------------------------
extern "C" void kernel_launch(void* const* d_in, const int* in_sizes, int n_in,
                              void* d_out, int out_size) {
    const float* x = (const float*)d_in[0];
    const float* m = (const float*)d_in[1];
    float* out = (float*)d_out;

    const int SMEM = 2 * STG_U32 * 4;   // 69632 B per CTA
    cudaFuncSetAttribute(k_gemm1, cudaFuncAttributeMaxDynamicSharedMemorySize, SMEM);
    cudaFuncSetAttribute(k_gemm2, cudaFuncAttributeMaxDynamicSharedMemorySize, SMEM);

    // zero accumulators via memset nodes (no alloc; graph-capturable)
    void *p_esum, *p_cnt, *p_rowsum, *p_amax;
    cudaGetSymbolAddress(&p_esum,   g_esum);
    cudaGetSymbolAddress(&p_cnt,    g_cnt);
    cudaGetSymbolAddress(&p_rowsum, g_rowsum);
    cudaGetSymbolAddress(&p_amax,   g_amax);
    cudaMemsetAsync(p_esum,   0, (size_t)KCOD * CDIM * sizeof(float));
    cudaMemsetAsync(p_cnt,    0, (size_t)KCOD * sizeof(float));
    cudaMemsetAsync(p_rowsum, 0, (size_t)NTOK * sizeof(float));
    cudaMemsetAsync(p_amax,   0, (size_t)NTOK * sizeof(unsigned long long));

    k_norm_pack<<<NTOK / 32, dim3(32, 8)>>>(x);
    k_prep_m<<<KCOD, 256>>>(m);
    k_gemm1<<<dim3(KCOD / 128, NTOK / 128), 128, SMEM>>>();
    k_scatter<<<NTOK / 32, dim3(32, 8)>>>();
    k_update<<<KCOD / 2, 256>>>(m);
    k_gemm2<<<dim3(CDIM / 128, NTOK / 128), 128, SMEM>>>(out);
}

// round 17
// speedup vs baseline: 1.0457x; 1.0358x over previous
#include <cuda_runtime.h>
#include <cuda_fp16.h>
#include <cstdint>

#define NTOK  32768
#define CDIM  512
#define KCOD  1024
#define HW    4096

// ---------------- scratch ----------------------------------------------------
__device__ float               g_rnx[NTOK];
__device__ float               g_rnm[KCOD];
__device__ float               g_rowsum[NTOK];
__device__ unsigned long long  g_amax[NTOK];
__device__ uint32_t            g_xh[NTOK * CDIM / 2];            // half2(x), [b][c/2][s]
__device__ uint32_t            g_mhT[(CDIM / 2) * KCOD];         // half2(m), [c/2][j]
__device__ uint32_t            g_expsH[(size_t)(KCOD / 2) * NTOK]; // half2(exp), [j/2][token]
__device__ float               g_esum[KCOD * CDIM];
__device__ float               g_cnt[KCOD];
__device__ uint32_t            g_newmH[(KCOD / 2) * CDIM];       // half2(new_m), [k/2][c]

// ---------------- helpers -----------------------------------------------------
__device__ __forceinline__ void cp16(void* dst, const void* src) {
    unsigned d = (unsigned)__cvta_generic_to_shared(dst);
    asm volatile("cp.async.cg.shared.global [%0], [%1], 16;" :: "r"(d), "l"(src));
}

#define MMA_F16(d, a, b) \
    asm volatile("mma.sync.aligned.m16n8k16.row.col.f32.f16.f16.f32 " \
        "{%0,%1,%2,%3}, {%4,%5,%6,%7}, {%8,%9}, {%0,%1,%2,%3};" \
        : "+f"(d[0]), "+f"(d[1]), "+f"(d[2]), "+f"(d[3]) \
        : "r"(a[0]), "r"(a[1]), "r"(a[2]), "r"(a[3]), "r"(b[0]), "r"(b[1]))

__device__ __forceinline__ uint32_t pack_h2(float lo, float hi) {
    __half2 h = __floats2half2_rn(lo, hi);
    return *(uint32_t*)&h;
}

__device__ __forceinline__ unsigned long long pack_max(float s, int j) {
    unsigned int bits = __float_as_uint(s);
    unsigned int key  = (bits & 0x80000000u) ? ~bits : (bits | 0x80000000u);
    return ((unsigned long long)key << 32)
         | (unsigned long long)(0xFFFFFFFFu - (unsigned)j);
}

// ---------------- fused: token norms + half2 pack + rowsum/amax zero --------------
__global__ void k_norm_pack(const float* __restrict__ x) {
    int i0 = blockIdx.x * 32;
    int b  = i0 >> 12;
    int s0 = i0 & 4095;
    int tx = threadIdx.x, ty = threadIdx.y;   // 32 x 8
    // zero this block's rowsum/amax (runs before k_gemm1's atomics)
    int tid = ty * 32 + tx;
    if (tid < 32) {
        g_rowsum[i0 + tid] = 0.f;
        g_amax[i0 + tid]   = 0ull;
    }
    const float* xb = x + (size_t)b * CDIM * HW + s0 + tx;
    uint32_t* xo = g_xh + (size_t)b * (CDIM / 2) * HW + s0 + tx;
    float ss = 0.f;
    for (int p = ty; p < CDIM / 2; p += 8) {
        float v0 = xb[(size_t)(2 * p)     * HW];
        float v1 = xb[(size_t)(2 * p + 1) * HW];
        ss += v0 * v0 + v1 * v1;
        xo[(size_t)p * HW] = pack_h2(v0, v1);
    }
    __shared__ float sm[8][33];
    sm[ty][tx] = ss;
    __syncthreads();
    if (ty == 0) {
        float t = 0.f;
        #pragma unroll
        for (int r = 0; r < 8; r++) t += sm[r][tx];
        g_rnx[i0 + tx] = 1.0f / fmaxf(sqrtf(t), 1e-12f);
    }
}

// ---------------- codebook: norm + half2 transpose + esum/cnt zero -----------------
__global__ void k_prep_m(const float* __restrict__ m) {
    int j = blockIdx.x;
    int t = threadIdx.x;
    // zero this code's esum row + count (runs before k_scatter's atomics)
    *(float2*)&g_esum[(size_t)j * CDIM + 2 * t] = make_float2(0.f, 0.f);
    if (t == 0) g_cnt[j] = 0.f;
    float v0 = m[j * CDIM + 2 * t];
    float v1 = m[j * CDIM + 2 * t + 1];
    float ss = v0 * v0 + v1 * v1;
    #pragma unroll
    for (int o = 16; o > 0; o >>= 1) ss += __shfl_xor_sync(0xffffffffu, ss, o);
    __shared__ float sm[8];
    if ((t & 31) == 0) sm[t >> 5] = ss;
    __syncthreads();
    if (t == 0) {
        float tt = 0.f;
        #pragma unroll
        for (int w = 0; w < 8; w++) tt += sm[w];
        g_rnm[j] = 1.0f / fmaxf(sqrtf(tt), 1e-12f);
    }
    g_mhT[(size_t)t * KCOD + j] = pack_h2(v0, v1);
}

// ======== GEMM machinery (R14 proven): CTA 128 threads (4 warps, 2m x 2n), =======
// ======== tile 128x128, warp tile 64x64, ktile 64 halfs, 2 cp.async stages =======
// stage: As 32x136 u32 + Bs 32x136 u32
#define STG_U32   8704
#define AS_U32    4352

#define GEMM_ISSUE(Ag, Bg, strideA, strideB, it) do {                        \
    uint32_t* dst = smem + ((it) & 1) * STG_U32;                             \
    int kr0 = (it) * 32;                                                     \
    _Pragma("unroll")                                                        \
    for (int q = 0; q < 8; q++) {                                            \
        int ch = tid + q * 128;                                              \
        int r = ch >> 5, cu = (ch & 31) * 4;                                 \
        cp16(&dst[r * 136 + cu], (Ag) + (size_t)(kr0 + r) * (strideA) + cu); \
        cp16(&dst[AS_U32 + r * 136 + cu],                                    \
             (Bg) + (size_t)(kr0 + r) * (strideB) + cu);                     \
    }                                                                        \
    asm volatile("cp.async.commit_group;");                                  \
} while (0)

#define GEMM_COMPUTE(it) do {                                                \
    const uint32_t* As = smem + ((it) & 1) * STG_U32;                        \
    const uint32_t* Bs = As + AS_U32;                                        \
    _Pragma("unroll")                                                        \
    for (int kp = 0; kp < 32; kp += 8) {                                     \
        uint32_t af[4][4], bf[8][2];                                         \
        _Pragma("unroll")                                                    \
        for (int mt = 0; mt < 4; mt++) {                                     \
            af[mt][0] = As[(kp + tg    ) * 136 + rA + mt * 16    ];          \
            af[mt][1] = As[(kp + tg    ) * 136 + rA + mt * 16 + 8];          \
            af[mt][2] = As[(kp + tg + 4) * 136 + rA + mt * 16    ];          \
            af[mt][3] = As[(kp + tg + 4) * 136 + rA + mt * 16 + 8];          \
        }                                                                    \
        _Pragma("unroll")                                                    \
        for (int nt = 0; nt < 8; nt++) {                                     \
            bf[nt][0] = Bs[(kp + tg    ) * 136 + cB + nt * 8];               \
            bf[nt][1] = Bs[(kp + tg + 4) * 136 + cB + nt * 8];               \
        }                                                                    \
        _Pragma("unroll")                                                    \
        for (int mt = 0; mt < 4; mt++)                                       \
            _Pragma("unroll")                                                \
            for (int nt = 0; nt < 8; nt++)                                   \
                MMA_F16(acc[mt][nt], af[mt], bf[nt]);                        \
    }                                                                        \
} while (0)

// 2-stage pipeline: wait -> compute -> barrier -> refill freed stage (R14 exact)
#define GEMM_MAINLOOP(Ag, Bg, strideA, strideB, NIT) do {                    \
    GEMM_ISSUE(Ag, Bg, strideA, strideB, 0);                                 \
    GEMM_ISSUE(Ag, Bg, strideA, strideB, 1);                                 \
    for (int it = 0; it < (NIT); it++) {                                     \
        if (it + 1 < (NIT)) { asm volatile("cp.async.wait_group 1;"); }      \
        else                { asm volatile("cp.async.wait_group 0;"); }      \
        __syncthreads();                                                     \
        GEMM_COMPUTE(it);                                                    \
        __syncthreads();                                                     \
        if (it + 2 < (NIT)) GEMM_ISSUE(Ag, Bg, strideA, strideB, it + 2);    \
    }                                                                        \
} while (0)

// ---------------- GEMM1: exp(score) + fused rowsum/argmax (fp16 mma) --------------
__global__ void __launch_bounds__(128, 2) k_gemm1() {
    extern __shared__ uint32_t smem[];
    int tid  = threadIdx.x;
    int lane = tid & 31, warp = tid >> 5;      // 4 warps
    int g = lane >> 2, tg = lane & 3;
    int wm = warp >> 1, wn = warp & 1;         // 2m x 2n
    int i0 = blockIdx.y * 128;
    int j0 = blockIdx.x * 128;
    int b  = i0 >> 12, s0 = i0 & 4095;
    const uint32_t* Ag = g_xh + (size_t)b * (CDIM / 2) * HW + s0;
    const uint32_t* Bg = g_mhT + j0;

    float acc[4][8][4] = {};
    const int NIT = CDIM / 64;      // 8
    int rA = wm * 64 + g;
    int cB = wn * 64 + g;

    GEMM_MAINLOOP(Ag, Bg, HW, KCOD, NIT);

    // epilogue (validated numerics)
    int rbase = i0 + wm * 64;
    int cbase = j0 + wn * 64 + 2 * tg;
    float rm0[8], rm1[8];
    #pragma unroll
    for (int nt = 0; nt < 8; nt++) {
        rm0[nt] = g_rnm[cbase + nt * 8];
        rm1[nt] = g_rnm[cbase + nt * 8 + 1];
    }
    #pragma unroll
    for (int mt = 0; mt < 4; mt++) {
        int r0 = rbase + mt * 16 + g;
        int r1 = r0 + 8;
        float rx0 = g_rnx[r0], rx1 = g_rnx[r1];
        float sum0 = 0.f, sum1 = 0.f;
        float best0 = -2.f, best1 = -2.f;
        int bj0 = cbase, bj1 = cbase;
        #pragma unroll
        for (int nt = 0; nt < 8; nt++) {
            int c = cbase + nt * 8;
            float s00 = acc[mt][nt][0] * rx0 * rm0[nt];
            float s01 = acc[mt][nt][1] * rx0 * rm1[nt];
            float s10 = acc[mt][nt][2] * rx1 * rm0[nt];
            float s11 = acc[mt][nt][3] * rx1 * rm1[nt];
            float e00 = __expf(s00), e01 = __expf(s01);
            float e10 = __expf(s10), e11 = __expf(s11);
            size_t cp = (size_t)(c >> 1) * NTOK;
            g_expsH[cp + r0] = pack_h2(e00, e01);
            g_expsH[cp + r1] = pack_h2(e10, e11);
            sum0 += e00 + e01; sum1 += e10 + e11;
            if (s00 > best0) { best0 = s00; bj0 = c; }
            if (s01 > best0) { best0 = s01; bj0 = c + 1; }
            if (s10 > best1) { best1 = s10; bj1 = c; }
            if (s11 > best1) { best1 = s11; bj1 = c + 1; }
        }
        unsigned long long p0 = pack_max(best0, bj0);
        unsigned long long p1 = pack_max(best1, bj1);
        #pragma unroll
        for (int o = 1; o < 4; o <<= 1) {
            sum0 += __shfl_xor_sync(0xffffffffu, sum0, o);
            sum1 += __shfl_xor_sync(0xffffffffu, sum1, o);
            unsigned long long q0 = __shfl_xor_sync(0xffffffffu, p0, o);
            unsigned long long q1 = __shfl_xor_sync(0xffffffffu, p1, o);
            if (q0 > p0) p0 = q0;
            if (q1 > p1) p1 = q1;
        }
        if (tg == 0) {
            atomicAdd(&g_rowsum[r0], sum0);
            atomicAdd(&g_rowsum[r1], sum1);
            atomicMax(&g_amax[r0], p0);
            atomicMax(&g_amax[r1], p1);
        }
    }
}

// ---------------- scatter: half2 reads + red.v4 vector reductions ------------------
__global__ void k_scatter() {
    int i0 = blockIdx.x * 32;
    int b  = i0 >> 12, s0 = i0 & 4095;
    int tx = threadIdx.x, ty = threadIdx.y;   // 32 x 8
    __shared__ int sidx[32];
    int tid = ty * 32 + tx;
    if (tid < 32) {
        unsigned long long p = g_amax[i0 + tid];
        int idx = (int)(0xFFFFFFFFu - (unsigned)(p & 0xFFFFFFFFull));
        sidx[tid] = idx;
        atomicAdd(&g_cnt[idx], 1.0f);
    }
    __syncthreads();
    int idx = sidx[tx];
    const uint32_t* xb = g_xh + (size_t)b * (CDIM / 2) * HW + s0 + tx;
    float* erow = g_esum + (size_t)idx * CDIM;
    for (int q = ty; q < CDIM / 4; q += 8) {
        uint32_t u0 = xb[(size_t)(2 * q)     * HW];
        uint32_t u1 = xb[(size_t)(2 * q + 1) * HW];
        __half2 h0 = *(__half2*)&u0;
        __half2 h1 = *(__half2*)&u1;
        float c0 = __low2float(h0), c1 = __high2float(h0);
        float c2 = __low2float(h1), c3 = __high2float(h1);
        asm volatile("red.global.add.v4.f32 [%0], {%1, %2, %3, %4};"
                     :: "l"(erow + 4 * q), "f"(c0), "f"(c1), "f"(c2), "f"(c3)
                     : "memory");
    }
}

// ---------------- EMA update -> half2 pairs along k -------------------------------
__global__ void k_update(const float* __restrict__ m) {
    int kp = blockIdx.x;
    int k0 = 2 * kp, k1 = k0 + 1;
    float inv0 = 0.001f / (g_cnt[k0] + 1e-6f);
    float inv1 = 0.001f / (g_cnt[k1] + 1e-6f);
    for (int j = threadIdx.x; j < CDIM; j += blockDim.x) {
        float v0 = m[k0 * CDIM + j] * 0.999f + g_esum[k0 * CDIM + j] * inv0;
        float v1 = m[k1 * CDIM + j] * 0.999f + g_esum[k1 * CDIM + j] * inv1;
        g_newmH[(size_t)kp * CDIM + j] = pack_h2(v0, v1);
    }
}

// ---------------- GEMM2: out = (exps @ new_m) / rowsum (fp16 mma) ------------------
__global__ void __launch_bounds__(128, 2) k_gemm2(float* __restrict__ out) {
    extern __shared__ uint32_t smem[];
    int tid  = threadIdx.x;
    int lane = tid & 31, warp = tid >> 5;
    int g = lane >> 2, tg = lane & 3;
    int wm = warp >> 1, wn = warp & 1;
    int i0 = blockIdx.y * 128;   // tokens
    int j0 = blockIdx.x * 128;   // channels

    const uint32_t* Ag = g_expsH + i0;
    const uint32_t* Bg = g_newmH + j0;

    float acc[4][8][4] = {};
    const int NIT = KCOD / 64;           // 16
    int rA = wm * 64 + g;
    int cB = wn * 64 + g;

    GEMM_MAINLOOP(Ag, Bg, NTOK, CDIM, NIT);

    int b = i0 >> 12;
    int rbase = i0 + wm * 64;
    int cbase = j0 + wn * 64 + 2 * tg;
    #pragma unroll
    for (int mt = 0; mt < 4; mt++) {
        int r0 = rbase + mt * 16 + g;
        int r1 = r0 + 8;
        float ri0 = 1.0f / g_rowsum[r0];
        float ri1 = 1.0f / g_rowsum[r1];
        int sA = r0 & 4095, sB = r1 & 4095;
        #pragma unroll
        for (int nt = 0; nt < 8; nt++) {
            int c = cbase + nt * 8;
            out[(size_t)(b * CDIM + c    ) * HW + sA] = acc[mt][nt][0] * ri0;
            out[(size_t)(b * CDIM + c + 1) * HW + sA] = acc[mt][nt][1] * ri0;
            out[(size_t)(b * CDIM + c    ) * HW + sB] = acc[mt][nt][2] * ri1;
            out[(size_t)(b * CDIM + c + 1) * HW + sB] = acc[mt][nt][3] * ri1;
        }
    }
}

// ---------------- launch -------------------------------------------------------------
extern "C" void kernel_launch(void* const* d_in, const int* in_sizes, int n_in,
                              void* d_out, int out_size) {
    const float* x = (const float*)d_in[0];
    const float* m = (const float*)d_in[1];
    float* out = (float*)d_out;

    const int SMEM = 2 * STG_U32 * 4;   // 69632 B per CTA
    cudaFuncSetAttribute(k_gemm1, cudaFuncAttributeMaxDynamicSharedMemorySize, SMEM);
    cudaFuncSetAttribute(k_gemm2, cudaFuncAttributeMaxDynamicSharedMemorySize, SMEM);

    k_norm_pack<<<NTOK / 32, dim3(32, 8)>>>(x);
    k_prep_m<<<KCOD, 256>>>(m);
    k_gemm1<<<dim3(KCOD / 128, NTOK / 128), 128, SMEM>>>();
    k_scatter<<<NTOK / 32, dim3(32, 8)>>>();
    k_update<<<KCOD / 2, 256>>>(m);
    k_gemm2<<<dim3(CDIM / 128, NTOK / 128), 128, SMEM>>>(out);
}